// round 3
// baseline (speedup 1.0000x reference)
#include <cuda_runtime.h>
#include <math.h>

// ---------------------------------------------------------------------------
// Qwen2MoeAttention: B=2, S=2048, H=2048, NH=16, NKV=4, HD=128, theta=1e6
// QKV GEMM (+bias) -> RoPE(q,k) -> GQA causal flash attention -> Wo GEMM
// f32x2 packed FMA everywhere; attention softmax is register+shuffle based.
// ---------------------------------------------------------------------------

#define QSTR 130   // Q/K smem row stride
#define VSTR 132   // V smem row stride (union buffer sized by this)
#define PSTR 65    // probs smem row stride

typedef unsigned long long u64;

static __device__ float g_qkv[4096 * 3072];   // [token][3072] : q(2048)|k(512)|v(512)
static __device__ float g_attn[4096 * 2048];  // [token][NH*HD]

__device__ __forceinline__ u64 ffma2(u64 a, u64 b, u64 c) {
    u64 d;
    asm("fma.rn.f32x2 %0,%1,%2,%3;" : "=l"(d) : "l"(a), "l"(b), "l"(c));
    return d;
}
__device__ __forceinline__ u64 fmul2(u64 a, u64 b) {
    u64 d;
    asm("mul.rn.f32x2 %0,%1,%2;" : "=l"(d) : "l"(a), "l"(b));
    return d;
}
__device__ __forceinline__ u64 splat2(float x) {
    u64 d;
    asm("mov.b64 %0,{%1,%1};" : "=l"(d) : "r"(__float_as_uint(x)));
    return d;
}
__device__ __forceinline__ float2 unpack2(u64 a) {
    unsigned lo, hi;
    asm("mov.b64 {%0,%1},%2;" : "=r"(lo), "=r"(hi) : "l"(a));
    return make_float2(__uint_as_float(lo), __uint_as_float(hi));
}

// ---------------------------------------------------------------------------
// SGEMM: C[M,N] = A[M,K] @ B[K,N] (+ bias). 128x128 block, 8x8/thread, f32x2.
// (measured at FFMA2 issue roofline — unchanged this round)
// ---------------------------------------------------------------------------
__global__ __launch_bounds__(256) void sgemm_bias_kernel(
    const float* __restrict__ A, const float* __restrict__ Bm,
    const float* __restrict__ bias, float* __restrict__ C,
    int M, int N, int K)
{
    __shared__ float As[8][128];
    __shared__ float Bs[8][128];

    const int tid = threadIdx.x;
    const int tx = tid & 15;
    const int ty = tid >> 4;
    const int bm = blockIdx.y, bn = blockIdx.x;

    const int arow = tid >> 1;
    const int acol = (tid & 1) << 2;
    const int brow = tid >> 5;
    const int bcol = (tid & 31) << 2;

    const float* Aptr = A + (size_t)(bm * 128 + arow) * K + acol;
    const float* Bptr = Bm + (size_t)brow * N + bn * 128 + bcol;

    u64 c2[4][8];
#pragma unroll
    for (int i = 0; i < 4; i++)
#pragma unroll
        for (int j = 0; j < 8; j++) c2[i][j] = 0ull;

    float4 aR = *(const float4*)Aptr;
    float4 bR = *(const float4*)Bptr;
    const int ntiles = K >> 3;

    As[acol + 0][arow] = aR.x; As[acol + 1][arow] = aR.y;
    As[acol + 2][arow] = aR.z; As[acol + 3][arow] = aR.w;
    *(float4*)&Bs[brow][bcol] = bR;
    __syncthreads();

    for (int t = 1; t <= ntiles; t++) {
        if (t < ntiles) {
            aR = *(const float4*)(Aptr + t * 8);
            bR = *(const float4*)(Bptr + (size_t)t * 8 * N);
        }
#pragma unroll
        for (int kk = 0; kk < 8; kk++) {
            ulonglong2 a01 = *(const ulonglong2*)&As[kk][ty << 3];
            ulonglong2 a23 = *(const ulonglong2*)(&As[kk][ty << 3] + 4);
            float4 b03 = *(const float4*)&Bs[kk][tx << 3];
            float4 b47 = *(const float4*)(&Bs[kk][tx << 3] + 4);
            u64 a2[4] = {a01.x, a01.y, a23.x, a23.y};
            u64 b2[8] = {splat2(b03.x), splat2(b03.y), splat2(b03.z), splat2(b03.w),
                         splat2(b47.x), splat2(b47.y), splat2(b47.z), splat2(b47.w)};
#pragma unroll
            for (int i = 0; i < 4; i++)
#pragma unroll
                for (int j = 0; j < 8; j++) c2[i][j] = ffma2(a2[i], b2[j], c2[i][j]);
        }
        __syncthreads();
        if (t < ntiles) {
            As[acol + 0][arow] = aR.x; As[acol + 1][arow] = aR.y;
            As[acol + 2][arow] = aR.z; As[acol + 3][arow] = aR.w;
            *(float4*)&Bs[brow][bcol] = bR;
            __syncthreads();
        }
    }

    const int col0 = bn * 128 + (tx << 3);
    float bl[8];
#pragma unroll
    for (int j = 0; j < 8; j++) bl[j] = bias ? bias[col0 + j] : 0.0f;

#pragma unroll
    for (int i2 = 0; i2 < 4; i2++) {
        float lo[8], hi[8];
#pragma unroll
        for (int j = 0; j < 8; j++) {
            float2 v = unpack2(c2[i2][j]);
            lo[j] = v.x + bl[j];
            hi[j] = v.y + bl[j];
        }
        size_t r0 = (size_t)(bm * 128 + (ty << 3) + (i2 << 1));
        float* Crow = C + r0 * N + col0;
        *(float4*)Crow = make_float4(lo[0], lo[1], lo[2], lo[3]);
        *(float4*)(Crow + 4) = make_float4(lo[4], lo[5], lo[6], lo[7]);
        float* Crow2 = Crow + N;
        *(float4*)Crow2 = make_float4(hi[0], hi[1], hi[2], hi[3]);
        *(float4*)(Crow2 + 4) = make_float4(hi[4], hi[5], hi[6], hi[7]);
    }
}

// ---------------------------------------------------------------------------
// RoPE in-place on q (16 heads) and k (4 heads) inside g_qkv.
// ---------------------------------------------------------------------------
__global__ void rope_kernel(const int* __restrict__ positions, float* __restrict__ qkv) {
    const int token = blockIdx.x;
    const int hh = blockIdx.y;
    const int t = threadIdx.x;
    float* base = qkv + (size_t)token * 3072 +
                  (hh < 16 ? hh * 128 : 2048 + (hh - 16) * 128);
    const float pos = (float)positions[token];
    const float e = (float)(2 * t) * (1.0f / 128.0f);
    const float inv = 1.0f / powf(1000000.0f, e);
    const float ang = pos * inv;
    float sv, cv;
    sincosf(ang, &sv, &cv);
    const float x1 = base[t];
    const float x2 = base[t + 64];
    base[t]      = x1 * cv - x2 * sv;
    base[t + 64] = x2 * cv + x1 * sv;
}

// ---------------------------------------------------------------------------
// Flash attention: 64x64 tiles, register softmax with half-warp shuffles.
// grid (32,16,2), 256 threads (16x16). smem = Q(64*130) | KV union(64*132) |
// P(64*65) = 83712 B. Thread (ti,tj): scores i=ti+16r, j=tj+16c.
// Per chunk: load K; sync; scores(regs); sync; V-load + reg-softmax + P-store;
// sync; PV. 3 syncs/chunk (was 4 + serial 64-thread softmax pass).
// ---------------------------------------------------------------------------
__global__ __launch_bounds__(256) void attn_kernel(
    const float* __restrict__ qkv, float* __restrict__ outp)
{
    extern __shared__ float sm[];
    float* Qs = sm;                    // 64*QSTR
    float* Ks = Qs + 64 * QSTR;        // union: K (stride QSTR) / V (stride VSTR)
    float* Ps = Ks + 64 * VSTR;        // 64*PSTR

    const int tid = threadIdx.x;
    const int ti = tid >> 4;
    const int tj = tid & 15;
    const int qt = blockIdx.x;
    const int h = blockIdx.y;
    const int b = blockIdx.z;
    const int q0 = qt * 64;
    const int tb = b * 2048;
    const int kvh = h >> 2;

    const float* Qg = qkv + (size_t)(tb + q0) * 3072 + h * 128;
    const float* Kg = qkv + (size_t)tb * 3072 + 2048 + kvh * 128;
    const float* Vg = qkv + (size_t)tb * 3072 + 2560 + kvh * 128;
    const float scale = 0.08838834764831845f;  // 1/sqrt(128)

    // Q load (float4 vectorized)
    for (int idx = tid; idx < 64 * 32; idx += 256) {
        int i = idx >> 5, d4 = (idx & 31) << 2;
        float4 v = *(const float4*)(Qg + (size_t)i * 3072 + d4);
        float* q = &Qs[i * QSTR + d4];
        q[0] = v.x * scale; q[1] = v.y * scale; q[2] = v.z * scale; q[3] = v.w * scale;
    }

    float m_run[4], l_run[4];
#pragma unroll
    for (int r = 0; r < 4; r++) { m_run[r] = -3.0e38f; l_run[r] = 0.0f; }

    u64 acc2[4][4];
#pragma unroll
    for (int r = 0; r < 4; r++)
#pragma unroll
        for (int c = 0; c < 4; c++) acc2[r][c] = 0ull;
    __syncthreads();

    const int nck = qt + 1;
    for (int ck = 0; ck < nck; ck++) {
        const int k0 = ck * 64;
        // load K tile (float4)
        for (int idx = tid; idx < 64 * 32; idx += 256) {
            int j = idx >> 5, d4 = (idx & 31) << 2;
            float4 v = *(const float4*)(Kg + (size_t)(k0 + j) * 3072 + d4);
            float* kp = &Ks[j * QSTR + d4];
            kp[0] = v.x; kp[1] = v.y; kp[2] = v.z; kp[3] = v.w;
        }
        __syncthreads();

        // scores
        u64 s2[4][4];
#pragma unroll
        for (int r = 0; r < 4; r++)
#pragma unroll
            for (int c = 0; c < 4; c++) s2[r][c] = 0ull;

#pragma unroll 8
        for (int d2 = 0; d2 < 64; d2++) {
            u64 q2[4], k2[4];
#pragma unroll
            for (int r = 0; r < 4; r++)
                q2[r] = *(const u64*)&Qs[(ti + 16 * r) * QSTR + 2 * d2];
#pragma unroll
            for (int c = 0; c < 4; c++)
                k2[c] = *(const u64*)&Ks[(tj + 16 * c) * QSTR + 2 * d2];
#pragma unroll
            for (int r = 0; r < 4; r++)
#pragma unroll
                for (int c = 0; c < 4; c++) s2[r][c] = ffma2(q2[r], k2[c], s2[r][c]);
        }
        __syncthreads();   // done reading K; union buffer free for V

        // issue V loads early (latency hides under softmax below)
        for (int idx = tid; idx < 64 * 32; idx += 256) {
            int j = idx >> 5, d4 = (idx & 31) << 2;
            float4 v = *(const float4*)(Vg + (size_t)(k0 + j) * 3072 + d4);
            float* vp = &Ks[j * VSTR + d4];
            vp[0] = v.x; vp[1] = v.y; vp[2] = v.z; vp[3] = v.w;
        }

        // register softmax
        const bool diag = (ck == qt);
        float s[4][4];
#pragma unroll
        for (int r = 0; r < 4; r++)
#pragma unroll
            for (int c = 0; c < 4; c++) {
                float2 v = unpack2(s2[r][c]);
                float sv = v.x + v.y;
                if (diag && (tj + 16 * c) > (ti + 16 * r)) sv = -3.0e38f;
                s[r][c] = sv;
            }

#pragma unroll
        for (int r = 0; r < 4; r++) {
            float mx = fmaxf(fmaxf(s[r][0], s[r][1]), fmaxf(s[r][2], s[r][3]));
#pragma unroll
            for (int off = 8; off >= 1; off >>= 1)
                mx = fmaxf(mx, __shfl_xor_sync(0xffffffffu, mx, off));
            float mnew = fmaxf(m_run[r], mx);
            float alpha = __expf(m_run[r] - mnew);
            m_run[r] = mnew;
            float ls = 0.0f;
#pragma unroll
            for (int c = 0; c < 4; c++) {
                float p = __expf(s[r][c] - mnew);
                s[r][c] = p;
                ls += p;
            }
#pragma unroll
            for (int off = 8; off >= 1; off >>= 1)
                ls += __shfl_xor_sync(0xffffffffu, ls, off);
            l_run[r] = l_run[r] * alpha + ls;

            u64 al2 = splat2(alpha);
#pragma unroll
            for (int c = 0; c < 4; c++) acc2[r][c] = fmul2(acc2[r][c], al2);

            int i = ti + 16 * r;
#pragma unroll
            for (int c = 0; c < 4; c++) Ps[i * PSTR + tj + 16 * c] = s[r][c];
        }
        __syncthreads();   // V + P visible

        // PV
#pragma unroll 4
        for (int j = 0; j < 64; j++) {
            u64 p2[4];
#pragma unroll
            for (int r = 0; r < 4; r++) p2[r] = splat2(Ps[(ti + 16 * r) * PSTR + j]);
            u64 v2[4];
#pragma unroll
            for (int c = 0; c < 4; c++)
                v2[c] = *(const u64*)&Ks[j * VSTR + 2 * tj + 32 * c];
#pragma unroll
            for (int r = 0; r < 4; r++)
#pragma unroll
                for (int c = 0; c < 4; c++) acc2[r][c] = ffma2(p2[r], v2[c], acc2[r][c]);
        }
        __syncthreads();   // done reading V/P before next K overwrite
    }

    // epilogue
    float* Og = outp + (size_t)(tb + q0) * 2048 + h * 128;
#pragma unroll
    for (int r = 0; r < 4; r++) {
        int i = ti + 16 * r;
        float inv = 1.0f / l_run[r];
#pragma unroll
        for (int c = 0; c < 4; c++) {
            float2 v = unpack2(acc2[r][c]);
            int d = 2 * tj + 32 * c;
            *(float2*)&Og[(size_t)i * 2048 + d] = make_float2(v.x * inv, v.y * inv);
        }
    }
}

// ---------------------------------------------------------------------------
extern "C" void kernel_launch(void* const* d_in, const int* in_sizes, int n_in,
                              void* d_out, int out_size)
{
    const int* positions = (const int*)d_in[0];
    const float* hidden  = (const float*)d_in[1];
    const float* Wqkv    = (const float*)d_in[2];
    const float* bqkv    = (const float*)d_in[3];
    const float* Wo      = (const float*)d_in[4];
    float* out = (float*)d_out;

    float *qkv, *attn;
    cudaGetSymbolAddress((void**)&qkv, g_qkv);
    cudaGetSymbolAddress((void**)&attn, g_attn);

    sgemm_bias_kernel<<<dim3(3072 / 128, 4096 / 128), 256>>>(
        hidden, Wqkv, bqkv, qkv, 4096, 3072, 2048);

    rope_kernel<<<dim3(4096, 20), 64>>>(positions, qkv);

    const size_t ATTN_SMEM = (size_t)(64 * QSTR + 64 * VSTR + 64 * PSTR) * sizeof(float); // 83712
    cudaFuncSetAttribute(attn_kernel, cudaFuncAttributeMaxDynamicSharedMemorySize,
                         (int)ATTN_SMEM);
    attn_kernel<<<dim3(32, 16, 2), 256, ATTN_SMEM>>>(qkv, attn);

    sgemm_bias_kernel<<<dim3(2048 / 128, 4096 / 128), 256>>>(
        attn, Wo, nullptr, out, 4096, 2048, 2048);
}

// round 4
// speedup vs baseline: 1.6076x; 1.6076x over previous
#include <cuda_runtime.h>
#include <math.h>

// ---------------------------------------------------------------------------
// Qwen2MoeAttention: B=2, S=2048, H=2048, NH=16, NKV=4, HD=128, theta=1e6
// QKV GEMM (+bias) -> RoPE(q,k) -> GQA causal flash attention -> Wo GEMM
// R4: R2 attention structure (measured good) + 4-lane/row parallel softmax.
// ---------------------------------------------------------------------------

#define QSTR 130
#define VSTR 132
#define PSTR 65

typedef unsigned long long u64;

static __device__ float g_qkv[4096 * 3072];   // [token][3072] : q(2048)|k(512)|v(512)
static __device__ float g_attn[4096 * 2048];  // [token][NH*HD]

__device__ __forceinline__ u64 ffma2(u64 a, u64 b, u64 c) {
    u64 d;
    asm("fma.rn.f32x2 %0,%1,%2,%3;" : "=l"(d) : "l"(a), "l"(b), "l"(c));
    return d;
}
__device__ __forceinline__ u64 fmul2(u64 a, u64 b) {
    u64 d;
    asm("mul.rn.f32x2 %0,%1,%2;" : "=l"(d) : "l"(a), "l"(b));
    return d;
}
__device__ __forceinline__ u64 splat2(float x) {
    u64 d;
    asm("mov.b64 %0,{%1,%1};" : "=l"(d) : "r"(__float_as_uint(x)));
    return d;
}
__device__ __forceinline__ float2 unpack2(u64 a) {
    unsigned lo, hi;
    asm("mov.b64 {%0,%1},%2;" : "=r"(lo), "=r"(hi) : "l"(a));
    return make_float2(__uint_as_float(lo), __uint_as_float(hi));
}

// ---------------------------------------------------------------------------
// SGEMM: C[M,N] = A[M,K] @ B[K,N] (+ bias). 128x128 block, 8x8/thread, f32x2.
// (measured at FFMA2 issue roofline — unchanged)
// ---------------------------------------------------------------------------
__global__ __launch_bounds__(256) void sgemm_bias_kernel(
    const float* __restrict__ A, const float* __restrict__ Bm,
    const float* __restrict__ bias, float* __restrict__ C,
    int M, int N, int K)
{
    __shared__ float As[8][128];
    __shared__ float Bs[8][128];

    const int tid = threadIdx.x;
    const int tx = tid & 15;
    const int ty = tid >> 4;
    const int bm = blockIdx.y, bn = blockIdx.x;

    const int arow = tid >> 1;
    const int acol = (tid & 1) << 2;
    const int brow = tid >> 5;
    const int bcol = (tid & 31) << 2;

    const float* Aptr = A + (size_t)(bm * 128 + arow) * K + acol;
    const float* Bptr = Bm + (size_t)brow * N + bn * 128 + bcol;

    u64 c2[4][8];
#pragma unroll
    for (int i = 0; i < 4; i++)
#pragma unroll
        for (int j = 0; j < 8; j++) c2[i][j] = 0ull;

    float4 aR = *(const float4*)Aptr;
    float4 bR = *(const float4*)Bptr;
    const int ntiles = K >> 3;

    As[acol + 0][arow] = aR.x; As[acol + 1][arow] = aR.y;
    As[acol + 2][arow] = aR.z; As[acol + 3][arow] = aR.w;
    *(float4*)&Bs[brow][bcol] = bR;
    __syncthreads();

    for (int t = 1; t <= ntiles; t++) {
        if (t < ntiles) {
            aR = *(const float4*)(Aptr + t * 8);
            bR = *(const float4*)(Bptr + (size_t)t * 8 * N);
        }
#pragma unroll
        for (int kk = 0; kk < 8; kk++) {
            ulonglong2 a01 = *(const ulonglong2*)&As[kk][ty << 3];
            ulonglong2 a23 = *(const ulonglong2*)(&As[kk][ty << 3] + 4);
            float4 b03 = *(const float4*)&Bs[kk][tx << 3];
            float4 b47 = *(const float4*)(&Bs[kk][tx << 3] + 4);
            u64 a2[4] = {a01.x, a01.y, a23.x, a23.y};
            u64 b2[8] = {splat2(b03.x), splat2(b03.y), splat2(b03.z), splat2(b03.w),
                         splat2(b47.x), splat2(b47.y), splat2(b47.z), splat2(b47.w)};
#pragma unroll
            for (int i = 0; i < 4; i++)
#pragma unroll
                for (int j = 0; j < 8; j++) c2[i][j] = ffma2(a2[i], b2[j], c2[i][j]);
        }
        __syncthreads();
        if (t < ntiles) {
            As[acol + 0][arow] = aR.x; As[acol + 1][arow] = aR.y;
            As[acol + 2][arow] = aR.z; As[acol + 3][arow] = aR.w;
            *(float4*)&Bs[brow][bcol] = bR;
            __syncthreads();
        }
    }

    const int col0 = bn * 128 + (tx << 3);
    float bl[8];
#pragma unroll
    for (int j = 0; j < 8; j++) bl[j] = bias ? bias[col0 + j] : 0.0f;

#pragma unroll
    for (int i2 = 0; i2 < 4; i2++) {
        float lo[8], hi[8];
#pragma unroll
        for (int j = 0; j < 8; j++) {
            float2 v = unpack2(c2[i2][j]);
            lo[j] = v.x + bl[j];
            hi[j] = v.y + bl[j];
        }
        size_t r0 = (size_t)(bm * 128 + (ty << 3) + (i2 << 1));
        float* Crow = C + r0 * N + col0;
        *(float4*)Crow = make_float4(lo[0], lo[1], lo[2], lo[3]);
        *(float4*)(Crow + 4) = make_float4(lo[4], lo[5], lo[6], lo[7]);
        float* Crow2 = Crow + N;
        *(float4*)Crow2 = make_float4(hi[0], hi[1], hi[2], hi[3]);
        *(float4*)(Crow2 + 4) = make_float4(hi[4], hi[5], hi[6], hi[7]);
    }
}

// ---------------------------------------------------------------------------
// RoPE in-place on q (16 heads) and k (4 heads) inside g_qkv.
// ---------------------------------------------------------------------------
__global__ void rope_kernel(const int* __restrict__ positions, float* __restrict__ qkv) {
    const int token = blockIdx.x;
    const int hh = blockIdx.y;
    const int t = threadIdx.x;
    float* base = qkv + (size_t)token * 3072 +
                  (hh < 16 ? hh * 128 : 2048 + (hh - 16) * 128);
    const float pos = (float)positions[token];
    const float e = (float)(2 * t) * (1.0f / 128.0f);
    const float inv = 1.0f / powf(1000000.0f, e);
    const float ang = pos * inv;
    float sv, cv;
    sincosf(ang, &sv, &cv);
    const float x1 = base[t];
    const float x2 = base[t + 64];
    base[t]      = x1 * cv - x2 * sv;
    base[t + 64] = x2 * cv + x1 * sv;
}

// ---------------------------------------------------------------------------
// Flash attention: 64x64 tiles, R2 phase structure, parallel smem softmax.
// grid (32,16,2), 256 threads (16x16), dynamic smem 84480 B.
// ---------------------------------------------------------------------------
__global__ __launch_bounds__(256) void attn_kernel(
    const float* __restrict__ qkv, float* __restrict__ outp)
{
    extern __shared__ float sm[];
    float* Qs = sm;                    // 64*130
    float* Ks = Qs + 64 * QSTR;        // union: K (stride QSTR) / V (stride VSTR)
    float* Ps = Ks + 8448;             // 64*65
    float* mArr = Ps + 64 * PSTR;
    float* lArr = mArr + 64;
    float* aArr = lArr + 64;

    const int tid = threadIdx.x;
    const int ti = tid >> 4;
    const int tj = tid & 15;
    const int qt = blockIdx.x;
    const int h = blockIdx.y;
    const int b = blockIdx.z;
    const int q0 = qt * 64;
    const int tb = b * 2048;
    const int kvh = h >> 2;

    const float* Qg = qkv + (size_t)(tb + q0) * 3072 + h * 128;
    const float* Kg = qkv + (size_t)tb * 3072 + 2048 + kvh * 128;
    const float* Vg = qkv + (size_t)tb * 3072 + 2560 + kvh * 128;
    const float scale = 0.08838834764831845f;  // 1/sqrt(128)

    for (int idx = tid; idx < 64 * 32; idx += 256) {
        int i = idx >> 5, d4 = (idx & 31) << 2;
        float4 v = *(const float4*)(Qg + (size_t)i * 3072 + d4);
        float* q = &Qs[i * QSTR + d4];
        q[0] = v.x * scale; q[1] = v.y * scale; q[2] = v.z * scale; q[3] = v.w * scale;
    }
    if (tid < 64) { mArr[tid] = -3.0e38f; lArr[tid] = 0.0f; }

    u64 acc2[4][4];
#pragma unroll
    for (int r = 0; r < 4; r++)
#pragma unroll
        for (int c = 0; c < 4; c++) acc2[r][c] = 0ull;
    __syncthreads();

    const int nck = qt + 1;
    for (int ck = 0; ck < nck; ck++) {
        const int k0 = ck * 64;
        // load K tile (float4)
        for (int idx = tid; idx < 64 * 32; idx += 256) {
            int j = idx >> 5, d4 = (idx & 31) << 2;
            float4 v = *(const float4*)(Kg + (size_t)(k0 + j) * 3072 + d4);
            float* kp = &Ks[j * QSTR + d4];
            kp[0] = v.x; kp[1] = v.y; kp[2] = v.z; kp[3] = v.w;
        }
        __syncthreads();

        // scores: s(i,j) = sum_d Qs[i][d]*Ks[j][d]
        u64 s2[4][4];
#pragma unroll
        for (int r = 0; r < 4; r++)
#pragma unroll
            for (int c = 0; c < 4; c++) s2[r][c] = 0ull;

#pragma unroll 8
        for (int d2 = 0; d2 < 64; d2++) {
            u64 q2[4], k2[4];
#pragma unroll
            for (int r = 0; r < 4; r++)
                q2[r] = *(const u64*)&Qs[(ti + 16 * r) * QSTR + 2 * d2];
#pragma unroll
            for (int c = 0; c < 4; c++)
                k2[c] = *(const u64*)&Ks[(tj + 16 * c) * QSTR + 2 * d2];
#pragma unroll
            for (int r = 0; r < 4; r++)
#pragma unroll
                for (int c = 0; c < 4; c++) s2[r][c] = ffma2(q2[r], k2[c], s2[r][c]);
        }

        const bool diag = (ck == qt);
#pragma unroll
        for (int r = 0; r < 4; r++)
#pragma unroll
            for (int c = 0; c < 4; c++) {
                float2 v = unpack2(s2[r][c]);
                float s = v.x + v.y;
                int i = ti + 16 * r, j = tj + 16 * c;
                if (diag && j > i) s = -3.0e38f;
                Ps[i * PSTR + j] = s;
            }
        __syncthreads();

        // parallel softmax: 4 lanes per row (same warp), 16 entries each
        {
            const int row = tid >> 2;
            const int part = tid & 3;
            float* prow = &Ps[row * PSTR + part * 16];
            float mloc = -3.0e38f;
#pragma unroll
            for (int jj = 0; jj < 16; jj++) mloc = fmaxf(mloc, prow[jj]);
            mloc = fmaxf(mloc, __shfl_xor_sync(0xffffffffu, mloc, 1));
            mloc = fmaxf(mloc, __shfl_xor_sync(0xffffffffu, mloc, 2));
            float mold = mArr[row];
            float mc = fmaxf(mold, mloc);
            float lsum = 0.0f;
#pragma unroll
            for (int jj = 0; jj < 16; jj++) {
                float p = __expf(prow[jj] - mc);
                prow[jj] = p;
                lsum += p;
            }
            lsum += __shfl_xor_sync(0xffffffffu, lsum, 1);
            lsum += __shfl_xor_sync(0xffffffffu, lsum, 2);
            if (part == 0) {
                float alpha = __expf(mold - mc);
                mArr[row] = mc;
                lArr[row] = lArr[row] * alpha + lsum;
                aArr[row] = alpha;
            }
        }
        __syncthreads();

        // rescale accumulators, then load V into the K/V union buffer
        u64 al2[4];
#pragma unroll
        for (int r = 0; r < 4; r++) al2[r] = splat2(aArr[ti + 16 * r]);
#pragma unroll
        for (int r = 0; r < 4; r++)
#pragma unroll
            for (int c = 0; c < 4; c++) acc2[r][c] = fmul2(acc2[r][c], al2[r]);

        for (int idx = tid; idx < 64 * 32; idx += 256) {
            int j = idx >> 5, d4 = (idx & 31) << 2;
            float4 v = *(const float4*)(Vg + (size_t)(k0 + j) * 3072 + d4);
            float* vp = &Ks[j * VSTR + d4];
            vp[0] = v.x; vp[1] = v.y; vp[2] = v.z; vp[3] = v.w;
        }
        __syncthreads();

        // PV: o(i,d) += P(i,j)*V(j,d)
#pragma unroll 4
        for (int j = 0; j < 64; j++) {
            u64 p2[4];
#pragma unroll
            for (int r = 0; r < 4; r++) p2[r] = splat2(Ps[(ti + 16 * r) * PSTR + j]);
            u64 v2[4];
#pragma unroll
            for (int c = 0; c < 4; c++)
                v2[c] = *(const u64*)&Ks[j * VSTR + 2 * tj + 32 * c];
#pragma unroll
            for (int r = 0; r < 4; r++)
#pragma unroll
                for (int c = 0; c < 4; c++) acc2[r][c] = ffma2(p2[r], v2[c], acc2[r][c]);
        }
        __syncthreads();
    }

    // epilogue
    float* Og = outp + (size_t)(tb + q0) * 2048 + h * 128;
#pragma unroll
    for (int r = 0; r < 4; r++) {
        int i = ti + 16 * r;
        float inv = 1.0f / lArr[i];
#pragma unroll
        for (int c = 0; c < 4; c++) {
            float2 v = unpack2(acc2[r][c]);
            int d = 2 * tj + 32 * c;
            *(float2*)&Og[(size_t)i * 2048 + d] = make_float2(v.x * inv, v.y * inv);
        }
    }
}

// ---------------------------------------------------------------------------
extern "C" void kernel_launch(void* const* d_in, const int* in_sizes, int n_in,
                              void* d_out, int out_size)
{
    const int* positions = (const int*)d_in[0];
    const float* hidden  = (const float*)d_in[1];
    const float* Wqkv    = (const float*)d_in[2];
    const float* bqkv    = (const float*)d_in[3];
    const float* Wo      = (const float*)d_in[4];
    float* out = (float*)d_out;

    float *qkv, *attn;
    cudaGetSymbolAddress((void**)&qkv, g_qkv);
    cudaGetSymbolAddress((void**)&attn, g_attn);

    sgemm_bias_kernel<<<dim3(3072 / 128, 4096 / 128), 256>>>(
        hidden, Wqkv, bqkv, qkv, 4096, 3072, 2048);

    rope_kernel<<<dim3(4096, 20), 64>>>(positions, qkv);

    const size_t ATTN_SMEM = (size_t)(64 * QSTR + 8448 + 64 * PSTR + 192) * sizeof(float); // 84480
    cudaFuncSetAttribute(attn_kernel, cudaFuncAttributeMaxDynamicSharedMemorySize,
                         (int)ATTN_SMEM);
    attn_kernel<<<dim3(32, 16, 2), 256, ATTN_SMEM>>>(qkv, attn);

    sgemm_bias_kernel<<<dim3(2048 / 128, 4096 / 128), 256>>>(
        attn, Wo, nullptr, out, 4096, 2048, 2048);
}

// round 6
// speedup vs baseline: 2.4237x; 1.5077x over previous
#include <cuda_runtime.h>
#include <cuda_bf16.h>
#include <math.h>

// ---------------------------------------------------------------------------
// Qwen2MoeAttention: B=2, S=2048, H=2048, NH=16, NKV=4, HD=128, theta=1e6
// R6: GEMMs on mma.sync (HMMA) bf16 3-term split, fp32 reg accum.
//     (tcgen05 unavailable: harness compiles via compute_103 virtual arch.)
//     Attention unchanged from R4.
// ---------------------------------------------------------------------------

#define QSTR 130
#define VSTR 132
#define PSTR 65

typedef unsigned long long u64;
typedef unsigned int u32;

static __device__ float g_qkv[4096 * 3072];
static __device__ float g_attn[4096 * 2048];
static __device__ __nv_bfloat16 g_Ahi[4096 * 2048];
static __device__ __nv_bfloat16 g_Alo[4096 * 2048];
static __device__ __nv_bfloat16 g_Bhi[3072 * 2048];   // [N][K] K-major
static __device__ __nv_bfloat16 g_Blo[3072 * 2048];

// ---------------- f32x2 helpers (attention) ----------------
__device__ __forceinline__ u64 ffma2(u64 a, u64 b, u64 c) {
    u64 d; asm("fma.rn.f32x2 %0,%1,%2,%3;" : "=l"(d) : "l"(a), "l"(b), "l"(c)); return d;
}
__device__ __forceinline__ u64 fmul2(u64 a, u64 b) {
    u64 d; asm("mul.rn.f32x2 %0,%1,%2;" : "=l"(d) : "l"(a), "l"(b)); return d;
}
__device__ __forceinline__ u64 splat2(float x) {
    u64 d; asm("mov.b64 %0,{%1,%1};" : "=l"(d) : "r"(__float_as_uint(x))); return d;
}
__device__ __forceinline__ float2 unpack2(u64 a) {
    unsigned lo, hi; asm("mov.b64 {%0,%1},%2;" : "=r"(lo), "=r"(hi) : "l"(a));
    return make_float2(__uint_as_float(lo), __uint_as_float(hi));
}

__device__ __forceinline__ u32 smem_u32(const void* p) {
    u32 a;
    asm("{ .reg .u64 t; cvta.to.shared.u64 t, %1; cvt.u32.u64 %0, t; }" : "=r"(a) : "l"(p));
    return a;
}

#define LDMX4(r0, r1, r2, r3, addr) \
    asm volatile("ldmatrix.sync.aligned.m8n8.x4.shared.b16 {%0,%1,%2,%3}, [%4];" \
                 : "=r"(r0), "=r"(r1), "=r"(r2), "=r"(r3) : "r"(addr))
#define LDMX2(r0, r1, addr) \
    asm volatile("ldmatrix.sync.aligned.m8n8.x2.shared.b16 {%0,%1}, [%2];" \
                 : "=r"(r0), "=r"(r1) : "r"(addr))
#define MMA16816(d, a, b) \
    asm volatile("mma.sync.aligned.m16n8k16.row.col.f32.bf16.bf16.f32 " \
                 "{%0,%1,%2,%3},{%4,%5,%6,%7},{%8,%9},{%0,%1,%2,%3};" \
                 : "+f"((d)[0]), "+f"((d)[1]), "+f"((d)[2]), "+f"((d)[3]) \
                 : "r"((a)[0]), "r"((a)[1]), "r"((a)[2]), "r"((a)[3]), \
                   "r"((b)[0]), "r"((b)[1]))

// smem: 4 tiles of 128 rows x 64 bf16, padded stride 72 bf16 (144 B)
#define TSTR 144                    // bytes per row
#define TILE_BYTES (128 * TSTR)     // 18432
#define OFF_AHI 0
#define OFF_ALO TILE_BYTES
#define OFF_BHI (2 * TILE_BYTES)
#define OFF_BLO (3 * TILE_BYTES)
#define GEMM_SMEM (4 * TILE_BYTES)  // 73728

// ---------------------------------------------------------------------------
// HMMA GEMM: C[M,N] = (Ahi+Alo)[M,K] @ (Bhi+Blo)[N,K]^T (+bias), 3-term split.
// CTA 128x128, 8 warps (2m x 4n), warp tile 64x32, K-stage 64.
// ---------------------------------------------------------------------------
__global__ __launch_bounds__(256) void gemm_hmma3_kernel(
    const __nv_bfloat16* __restrict__ Ahi, const __nv_bfloat16* __restrict__ Alo,
    const __nv_bfloat16* __restrict__ Bhi, const __nv_bfloat16* __restrict__ Blo,
    const float* __restrict__ bias, float* __restrict__ C, int N, int K)
{
    extern __shared__ char smem[];
    const u32 sb = smem_u32(smem);
    const int tid = threadIdx.x;
    const int wid = tid >> 5;
    const int lane = tid & 31;
    const int m0 = blockIdx.y * 128, n0 = blockIdx.x * 128;
    const int m0w = (wid >> 2) * 64;       // warp m-offset in tile
    const int n0w = (wid & 3) * 32;        // warp n-offset in tile

    // ldmatrix lane-address components
    const int a_row = ((lane >> 3) & 1) * 8 + (lane & 7);   // within m16
    const int a_kh  = (lane >> 4) * 8;                      // k half
    const int b_row = lane & 7;                             // within n8
    const int b_kh  = ((lane >> 3) & 1) * 8;                // k half

    float acc[4][4][4];
#pragma unroll
    for (int tm = 0; tm < 4; tm++)
#pragma unroll
        for (int tn = 0; tn < 4; tn++)
#pragma unroll
            for (int r = 0; r < 4; r++) acc[tm][tn][r] = 0.0f;

    const int nstages = K >> 6;
    for (int s = 0; s < nstages; s++) {
        const int ks = s << 6;
        // load 4 tiles (128x64 bf16 each) as uint4
#pragma unroll
        for (int it = 0; it < 4; it++) {
            int idx = tid + it * 256;           // 0..1023
            int row = idx >> 3, c8 = (idx & 7) << 3;
            u32 so = (u32)(row * TSTR + c8 * 2);
            size_t ga = (size_t)(m0 + row) * K + ks + c8;
            size_t gb = (size_t)(n0 + row) * K + ks + c8;
            *(uint4*)(smem + OFF_AHI + so) = *(const uint4*)(Ahi + ga);
            *(uint4*)(smem + OFF_ALO + so) = *(const uint4*)(Alo + ga);
            *(uint4*)(smem + OFF_BHI + so) = *(const uint4*)(Bhi + gb);
            *(uint4*)(smem + OFF_BLO + so) = *(const uint4*)(Blo + gb);
        }
        __syncthreads();

#pragma unroll
        for (int k16 = 0; k16 < 4; k16++) {
            const int k0 = k16 << 4;
            u32 ahi[4][4], alo[4][4], bhi[4][2], blo[4][2];
#pragma unroll
            for (int tm = 0; tm < 4; tm++) {
                u32 ao = (u32)((m0w + tm * 16 + a_row) * TSTR + (k0 + a_kh) * 2);
                LDMX4(ahi[tm][0], ahi[tm][1], ahi[tm][2], ahi[tm][3], sb + OFF_AHI + ao);
                LDMX4(alo[tm][0], alo[tm][1], alo[tm][2], alo[tm][3], sb + OFF_ALO + ao);
            }
#pragma unroll
            for (int tn = 0; tn < 4; tn++) {
                u32 bo = (u32)((n0w + tn * 8 + b_row) * TSTR + (k0 + b_kh) * 2);
                LDMX2(bhi[tn][0], bhi[tn][1], sb + OFF_BHI + bo);
                LDMX2(blo[tn][0], blo[tn][1], sb + OFF_BLO + bo);
            }
#pragma unroll
            for (int tm = 0; tm < 4; tm++)
#pragma unroll
                for (int tn = 0; tn < 4; tn++) {
                    MMA16816(acc[tm][tn], ahi[tm], bhi[tn]);
                    MMA16816(acc[tm][tn], ahi[tm], blo[tn]);
                    MMA16816(acc[tm][tn], alo[tm], bhi[tn]);
                }
        }
        __syncthreads();
    }

    // epilogue
#pragma unroll
    for (int tm = 0; tm < 4; tm++) {
        const int r0 = m0 + m0w + tm * 16 + (lane >> 2);
#pragma unroll
        for (int tn = 0; tn < 4; tn++) {
            const int c = n0 + n0w + tn * 8 + (lane & 3) * 2;
            float b0 = 0.0f, b1 = 0.0f;
            if (bias) { b0 = bias[c]; b1 = bias[c + 1]; }
            *(float2*)(C + (size_t)r0 * N + c) =
                make_float2(acc[tm][tn][0] + b0, acc[tm][tn][1] + b1);
            *(float2*)(C + (size_t)(r0 + 8) * N + c) =
                make_float2(acc[tm][tn][2] + b0, acc[tm][tn][3] + b1);
        }
    }
}

// ---------------------------------------------------------------------------
// fp32 -> bf16 hi/lo split (A-side)
// ---------------------------------------------------------------------------
__global__ __launch_bounds__(256) void convA_kernel(
    const float* __restrict__ A, __nv_bfloat16* __restrict__ hi,
    __nv_bfloat16* __restrict__ lo)
{
    const int i = (blockIdx.x * 256 + threadIdx.x) * 4;
    float4 v = *(const float4*)(A + i);
    __nv_bfloat16 h[4], l[4];
    float x[4] = {v.x, v.y, v.z, v.w};
#pragma unroll
    for (int j = 0; j < 4; j++) {
        h[j] = __float2bfloat16(x[j]);
        l[j] = __float2bfloat16(x[j] - __bfloat162float(h[j]));
    }
    *(uint2*)(hi + i) = *(uint2*)h;
    *(uint2*)(lo + i) = *(uint2*)l;
}

// ---------------------------------------------------------------------------
// W[K,N] fp32 -> Bhi/Blo[N,K] bf16 (transpose + split)
// ---------------------------------------------------------------------------
__global__ __launch_bounds__(256) void convW_kernel(
    const float* __restrict__ W, __nv_bfloat16* __restrict__ Bh,
    __nv_bfloat16* __restrict__ Bl, int K, int N)
{
    __shared__ float t[32][33];
    const int n0 = blockIdx.x * 32, k0 = blockIdx.y * 32;
    const int tx = threadIdx.x, ty = threadIdx.y;
#pragma unroll
    for (int i = 0; i < 32; i += 8)
        t[ty + i][tx] = W[(size_t)(k0 + ty + i) * N + n0 + tx];
    __syncthreads();
#pragma unroll
    for (int i = 0; i < 32; i += 8) {
        float x = t[tx][ty + i];
        __nv_bfloat16 h = __float2bfloat16(x);
        __nv_bfloat16 l = __float2bfloat16(x - __bfloat162float(h));
        size_t o = (size_t)(n0 + ty + i) * K + k0 + tx;
        Bh[o] = h;
        Bl[o] = l;
    }
}

// ---------------------------------------------------------------------------
// RoPE (unchanged)
// ---------------------------------------------------------------------------
__global__ void rope_kernel(const int* __restrict__ positions, float* __restrict__ qkv) {
    const int token = blockIdx.x;
    const int hh = blockIdx.y;
    const int t = threadIdx.x;
    float* base = qkv + (size_t)token * 3072 +
                  (hh < 16 ? hh * 128 : 2048 + (hh - 16) * 128);
    const float pos = (float)positions[token];
    const float e = (float)(2 * t) * (1.0f / 128.0f);
    const float inv = 1.0f / powf(1000000.0f, e);
    const float ang = pos * inv;
    float sv, cv;
    sincosf(ang, &sv, &cv);
    const float x1 = base[t];
    const float x2 = base[t + 64];
    base[t]      = x1 * cv - x2 * sv;
    base[t + 64] = x2 * cv + x1 * sv;
}

// ---------------------------------------------------------------------------
// Flash attention (unchanged from R4)
// ---------------------------------------------------------------------------
__global__ __launch_bounds__(256) void attn_kernel(
    const float* __restrict__ qkv, float* __restrict__ outp)
{
    extern __shared__ float sm[];
    float* Qs = sm;
    float* Ks = Qs + 64 * QSTR;
    float* Ps = Ks + 8448;
    float* mArr = Ps + 64 * PSTR;
    float* lArr = mArr + 64;
    float* aArr = lArr + 64;

    const int tid = threadIdx.x;
    const int ti = tid >> 4;
    const int tj = tid & 15;
    const int qt = blockIdx.x;
    const int h = blockIdx.y;
    const int b = blockIdx.z;
    const int q0 = qt * 64;
    const int tb = b * 2048;
    const int kvh = h >> 2;

    const float* Qg = qkv + (size_t)(tb + q0) * 3072 + h * 128;
    const float* Kg = qkv + (size_t)tb * 3072 + 2048 + kvh * 128;
    const float* Vg = qkv + (size_t)tb * 3072 + 2560 + kvh * 128;
    const float scale = 0.08838834764831845f;

    for (int idx = tid; idx < 64 * 32; idx += 256) {
        int i = idx >> 5, d4 = (idx & 31) << 2;
        float4 v = *(const float4*)(Qg + (size_t)i * 3072 + d4);
        float* q = &Qs[i * QSTR + d4];
        q[0] = v.x * scale; q[1] = v.y * scale; q[2] = v.z * scale; q[3] = v.w * scale;
    }
    if (tid < 64) { mArr[tid] = -3.0e38f; lArr[tid] = 0.0f; }

    u64 acc2[4][4];
#pragma unroll
    for (int r = 0; r < 4; r++)
#pragma unroll
        for (int c = 0; c < 4; c++) acc2[r][c] = 0ull;
    __syncthreads();

    const int nck = qt + 1;
    for (int ck = 0; ck < nck; ck++) {
        const int k0 = ck * 64;
        for (int idx = tid; idx < 64 * 32; idx += 256) {
            int j = idx >> 5, d4 = (idx & 31) << 2;
            float4 v = *(const float4*)(Kg + (size_t)(k0 + j) * 3072 + d4);
            float* kp = &Ks[j * QSTR + d4];
            kp[0] = v.x; kp[1] = v.y; kp[2] = v.z; kp[3] = v.w;
        }
        __syncthreads();

        u64 s2[4][4];
#pragma unroll
        for (int r = 0; r < 4; r++)
#pragma unroll
            for (int c = 0; c < 4; c++) s2[r][c] = 0ull;

#pragma unroll 8
        for (int d2 = 0; d2 < 64; d2++) {
            u64 q2[4], k2[4];
#pragma unroll
            for (int r = 0; r < 4; r++)
                q2[r] = *(const u64*)&Qs[(ti + 16 * r) * QSTR + 2 * d2];
#pragma unroll
            for (int c = 0; c < 4; c++)
                k2[c] = *(const u64*)&Ks[(tj + 16 * c) * QSTR + 2 * d2];
#pragma unroll
            for (int r = 0; r < 4; r++)
#pragma unroll
                for (int c = 0; c < 4; c++) s2[r][c] = ffma2(q2[r], k2[c], s2[r][c]);
        }

        const bool diag = (ck == qt);
#pragma unroll
        for (int r = 0; r < 4; r++)
#pragma unroll
            for (int c = 0; c < 4; c++) {
                float2 v = unpack2(s2[r][c]);
                float s = v.x + v.y;
                int i = ti + 16 * r, j = tj + 16 * c;
                if (diag && j > i) s = -3.0e38f;
                Ps[i * PSTR + j] = s;
            }
        __syncthreads();

        {
            const int row = tid >> 2;
            const int part = tid & 3;
            float* prow = &Ps[row * PSTR + part * 16];
            float mloc = -3.0e38f;
#pragma unroll
            for (int jj = 0; jj < 16; jj++) mloc = fmaxf(mloc, prow[jj]);
            mloc = fmaxf(mloc, __shfl_xor_sync(0xffffffffu, mloc, 1));
            mloc = fmaxf(mloc, __shfl_xor_sync(0xffffffffu, mloc, 2));
            float mold = mArr[row];
            float mc = fmaxf(mold, mloc);
            float lsum = 0.0f;
#pragma unroll
            for (int jj = 0; jj < 16; jj++) {
                float p = __expf(prow[jj] - mc);
                prow[jj] = p;
                lsum += p;
            }
            lsum += __shfl_xor_sync(0xffffffffu, lsum, 1);
            lsum += __shfl_xor_sync(0xffffffffu, lsum, 2);
            if (part == 0) {
                float alpha = __expf(mold - mc);
                mArr[row] = mc;
                lArr[row] = lArr[row] * alpha + lsum;
                aArr[row] = alpha;
            }
        }
        __syncthreads();

        u64 al2[4];
#pragma unroll
        for (int r = 0; r < 4; r++) al2[r] = splat2(aArr[ti + 16 * r]);
#pragma unroll
        for (int r = 0; r < 4; r++)
#pragma unroll
            for (int c = 0; c < 4; c++) acc2[r][c] = fmul2(acc2[r][c], al2[r]);

        for (int idx = tid; idx < 64 * 32; idx += 256) {
            int j = idx >> 5, d4 = (idx & 31) << 2;
            float4 v = *(const float4*)(Vg + (size_t)(k0 + j) * 3072 + d4);
            float* vp = &Ks[j * VSTR + d4];
            vp[0] = v.x; vp[1] = v.y; vp[2] = v.z; vp[3] = v.w;
        }
        __syncthreads();

#pragma unroll 4
        for (int j = 0; j < 64; j++) {
            u64 p2[4];
#pragma unroll
            for (int r = 0; r < 4; r++) p2[r] = splat2(Ps[(ti + 16 * r) * PSTR + j]);
            u64 v2[4];
#pragma unroll
            for (int c = 0; c < 4; c++)
                v2[c] = *(const u64*)&Ks[j * VSTR + 2 * tj + 32 * c];
#pragma unroll
            for (int r = 0; r < 4; r++)
#pragma unroll
                for (int c = 0; c < 4; c++) acc2[r][c] = ffma2(p2[r], v2[c], acc2[r][c]);
        }
        __syncthreads();
    }

    float* Og = outp + (size_t)(tb + q0) * 2048 + h * 128;
#pragma unroll
    for (int r = 0; r < 4; r++) {
        int i = ti + 16 * r;
        float inv = 1.0f / lArr[i];
#pragma unroll
        for (int c = 0; c < 4; c++) {
            float2 v = unpack2(acc2[r][c]);
            int d = 2 * tj + 32 * c;
            *(float2*)&Og[(size_t)i * 2048 + d] = make_float2(v.x * inv, v.y * inv);
        }
    }
}

// ---------------------------------------------------------------------------
extern "C" void kernel_launch(void* const* d_in, const int* in_sizes, int n_in,
                              void* d_out, int out_size)
{
    const int* positions = (const int*)d_in[0];
    const float* hidden  = (const float*)d_in[1];
    const float* Wqkv    = (const float*)d_in[2];
    const float* bqkv    = (const float*)d_in[3];
    const float* Wo      = (const float*)d_in[4];
    float* out = (float*)d_out;

    float *qkv, *attn;
    __nv_bfloat16 *Ahi, *Alo, *Bhi, *Blo;
    cudaGetSymbolAddress((void**)&qkv, g_qkv);
    cudaGetSymbolAddress((void**)&attn, g_attn);
    cudaGetSymbolAddress((void**)&Ahi, g_Ahi);
    cudaGetSymbolAddress((void**)&Alo, g_Alo);
    cudaGetSymbolAddress((void**)&Bhi, g_Bhi);
    cudaGetSymbolAddress((void**)&Blo, g_Blo);

    cudaFuncSetAttribute(gemm_hmma3_kernel,
                         cudaFuncAttributeMaxDynamicSharedMemorySize, GEMM_SMEM);

    // 1) split hidden -> bf16 hi/lo ; transpose+split Wqkv
    convA_kernel<<<4096 * 2048 / 1024, 256>>>(hidden, Ahi, Alo);
    convW_kernel<<<dim3(3072 / 32, 2048 / 32), dim3(32, 8)>>>(Wqkv, Bhi, Blo, 2048, 3072);

    // 2) QKV GEMM (HMMA) + bias
    gemm_hmma3_kernel<<<dim3(24, 32), 256, GEMM_SMEM>>>(
        Ahi, Alo, Bhi, Blo, bqkv, qkv, 3072, 2048);

    // 3) RoPE
    rope_kernel<<<dim3(4096, 20), 64>>>(positions, qkv);

    // 4) attention (fp32)
    const size_t ATTN_SMEM = (size_t)(64 * QSTR + 8448 + 64 * PSTR + 192) * sizeof(float);
    cudaFuncSetAttribute(attn_kernel, cudaFuncAttributeMaxDynamicSharedMemorySize,
                         (int)ATTN_SMEM);
    attn_kernel<<<dim3(32, 16, 2), 256, ATTN_SMEM>>>(qkv, attn);

    // 5) split attn ; transpose+split Wo ; Wo GEMM (HMMA)
    convA_kernel<<<4096 * 2048 / 1024, 256>>>(attn, Ahi, Alo);
    convW_kernel<<<dim3(2048 / 32, 2048 / 32), dim3(32, 8)>>>(Wo, Bhi, Blo, 2048, 2048);
    gemm_hmma3_kernel<<<dim3(16, 32), 256, GEMM_SMEM>>>(
        Ahi, Alo, Bhi, Blo, nullptr, out, 2048, 2048);
}

// round 7
// speedup vs baseline: 3.5968x; 1.4840x over previous
#include <cuda_runtime.h>
#include <cuda_bf16.h>
#include <math.h>

// ---------------------------------------------------------------------------
// Qwen2MoeAttention: B=2, S=2048, H=2048, NH=16, NKV=4, HD=128, theta=1e6
// R7: HMMA everywhere. GEMMs: bf16 3-term split (R6, unchanged).
//     Attention: HMMA flash kernel (3-term split QK^T and PV, frag softmax).
// ---------------------------------------------------------------------------

typedef unsigned long long u64;
typedef unsigned int u32;

static __device__ float g_qkv[4096 * 3072];
static __device__ __nv_bfloat16 g_qkvhi[4096 * 3072];
static __device__ __nv_bfloat16 g_qkvlo[4096 * 3072];
static __device__ __nv_bfloat16 g_Ahi[4096 * 2048];
static __device__ __nv_bfloat16 g_Alo[4096 * 2048];
static __device__ __nv_bfloat16 g_Bhi[3072 * 2048];   // [N][K] K-major
static __device__ __nv_bfloat16 g_Blo[3072 * 2048];

__device__ __forceinline__ u32 smem_u32(const void* p) {
    u32 a;
    asm("{ .reg .u64 t; cvta.to.shared.u64 t, %1; cvt.u32.u64 %0, t; }" : "=r"(a) : "l"(p));
    return a;
}

#define LDMX4(r0, r1, r2, r3, addr) \
    asm volatile("ldmatrix.sync.aligned.m8n8.x4.shared.b16 {%0,%1,%2,%3}, [%4];" \
                 : "=r"(r0), "=r"(r1), "=r"(r2), "=r"(r3) : "r"(addr))
#define LDMX2(r0, r1, addr) \
    asm volatile("ldmatrix.sync.aligned.m8n8.x2.shared.b16 {%0,%1}, [%2];" \
                 : "=r"(r0), "=r"(r1) : "r"(addr))
#define LDMX2T(r0, r1, addr) \
    asm volatile("ldmatrix.sync.aligned.m8n8.x2.trans.shared.b16 {%0,%1}, [%2];" \
                 : "=r"(r0), "=r"(r1) : "r"(addr))
#define MMA16816(d, a, b) \
    asm volatile("mma.sync.aligned.m16n8k16.row.col.f32.bf16.bf16.f32 " \
                 "{%0,%1,%2,%3},{%4,%5,%6,%7},{%8,%9},{%0,%1,%2,%3};" \
                 : "+f"((d)[0]), "+f"((d)[1]), "+f"((d)[2]), "+f"((d)[3]) \
                 : "r"((a)[0]), "r"((a)[1]), "r"((a)[2]), "r"((a)[3]), \
                   "r"((b)[0]), "r"((b)[1]))

__device__ __forceinline__ void cp16(u32 dst, const void* src) {
    asm volatile("cp.async.cg.shared.global [%0], [%1], 16;" :: "r"(dst), "l"(src));
}
#define CP_COMMIT() asm volatile("cp.async.commit_group;")
#define CP_WAIT0()  asm volatile("cp.async.wait_group 0;" ::: "memory")

__device__ __forceinline__ void splitpack(float x, float y, u32& hi, u32& lo) {
    __nv_bfloat162 h = __floats2bfloat162_rn(x, y);
    float hx = __bfloat162float(h.x), hy = __bfloat162float(h.y);
    __nv_bfloat162 l = __floats2bfloat162_rn(x - hx, y - hy);
    hi = *reinterpret_cast<u32*>(&h);
    lo = *reinterpret_cast<u32*>(&l);
}

// ======================= GEMM (unchanged from R6) ==========================
#define TSTR 144
#define TILE_BYTES (128 * TSTR)
#define OFF_AHI 0
#define OFF_ALO TILE_BYTES
#define OFF_BHI (2 * TILE_BYTES)
#define OFF_BLO (3 * TILE_BYTES)
#define GEMM_SMEM (4 * TILE_BYTES)

__global__ __launch_bounds__(256) void gemm_hmma3_kernel(
    const __nv_bfloat16* __restrict__ Ahi, const __nv_bfloat16* __restrict__ Alo,
    const __nv_bfloat16* __restrict__ Bhi, const __nv_bfloat16* __restrict__ Blo,
    const float* __restrict__ bias, float* __restrict__ C, int N, int K)
{
    extern __shared__ char smem[];
    const u32 sb = smem_u32(smem);
    const int tid = threadIdx.x;
    const int wid = tid >> 5;
    const int lane = tid & 31;
    const int m0 = blockIdx.y * 128, n0 = blockIdx.x * 128;
    const int m0w = (wid >> 2) * 64;
    const int n0w = (wid & 3) * 32;

    const int a_row = ((lane >> 3) & 1) * 8 + (lane & 7);
    const int a_kh  = (lane >> 4) * 8;
    const int b_row = lane & 7;
    const int b_kh  = ((lane >> 3) & 1) * 8;

    float acc[4][4][4];
#pragma unroll
    for (int tm = 0; tm < 4; tm++)
#pragma unroll
        for (int tn = 0; tn < 4; tn++)
#pragma unroll
            for (int r = 0; r < 4; r++) acc[tm][tn][r] = 0.0f;

    const int nstages = K >> 6;
    for (int s = 0; s < nstages; s++) {
        const int ks = s << 6;
#pragma unroll
        for (int it = 0; it < 4; it++) {
            int idx = tid + it * 256;
            int row = idx >> 3, c8 = (idx & 7) << 3;
            u32 so = (u32)(row * TSTR + c8 * 2);
            size_t ga = (size_t)(m0 + row) * K + ks + c8;
            size_t gb = (size_t)(n0 + row) * K + ks + c8;
            *(uint4*)(smem + OFF_AHI + so) = *(const uint4*)(Ahi + ga);
            *(uint4*)(smem + OFF_ALO + so) = *(const uint4*)(Alo + ga);
            *(uint4*)(smem + OFF_BHI + so) = *(const uint4*)(Bhi + gb);
            *(uint4*)(smem + OFF_BLO + so) = *(const uint4*)(Blo + gb);
        }
        __syncthreads();

#pragma unroll
        for (int k16 = 0; k16 < 4; k16++) {
            const int k0 = k16 << 4;
            u32 ahi[4][4], alo[4][4], bhi[4][2], blo[4][2];
#pragma unroll
            for (int tm = 0; tm < 4; tm++) {
                u32 ao = (u32)((m0w + tm * 16 + a_row) * TSTR + (k0 + a_kh) * 2);
                LDMX4(ahi[tm][0], ahi[tm][1], ahi[tm][2], ahi[tm][3], sb + OFF_AHI + ao);
                LDMX4(alo[tm][0], alo[tm][1], alo[tm][2], alo[tm][3], sb + OFF_ALO + ao);
            }
#pragma unroll
            for (int tn = 0; tn < 4; tn++) {
                u32 bo = (u32)((n0w + tn * 8 + b_row) * TSTR + (k0 + b_kh) * 2);
                LDMX2(bhi[tn][0], bhi[tn][1], sb + OFF_BHI + bo);
                LDMX2(blo[tn][0], blo[tn][1], sb + OFF_BLO + bo);
            }
#pragma unroll
            for (int tm = 0; tm < 4; tm++)
#pragma unroll
                for (int tn = 0; tn < 4; tn++) {
                    MMA16816(acc[tm][tn], ahi[tm], bhi[tn]);
                    MMA16816(acc[tm][tn], ahi[tm], blo[tn]);
                    MMA16816(acc[tm][tn], alo[tm], bhi[tn]);
                }
        }
        __syncthreads();
    }

#pragma unroll
    for (int tm = 0; tm < 4; tm++) {
        const int r0 = m0 + m0w + tm * 16 + (lane >> 2);
#pragma unroll
        for (int tn = 0; tn < 4; tn++) {
            const int c = n0 + n0w + tn * 8 + (lane & 3) * 2;
            float b0 = 0.0f, b1 = 0.0f;
            if (bias) { b0 = bias[c]; b1 = bias[c + 1]; }
            *(float2*)(C + (size_t)r0 * N + c) =
                make_float2(acc[tm][tn][0] + b0, acc[tm][tn][1] + b1);
            *(float2*)(C + (size_t)(r0 + 8) * N + c) =
                make_float2(acc[tm][tn][2] + b0, acc[tm][tn][3] + b1);
        }
    }
}

// ======================= conversions ==========================
__global__ __launch_bounds__(256) void convA_kernel(
    const float* __restrict__ A, __nv_bfloat16* __restrict__ hi,
    __nv_bfloat16* __restrict__ lo)
{
    const int i = (blockIdx.x * 256 + threadIdx.x) * 4;
    float4 v = *(const float4*)(A + i);
    __nv_bfloat16 h[4], l[4];
    float x[4] = {v.x, v.y, v.z, v.w};
#pragma unroll
    for (int j = 0; j < 4; j++) {
        h[j] = __float2bfloat16(x[j]);
        l[j] = __float2bfloat16(x[j] - __bfloat162float(h[j]));
    }
    *(uint2*)(hi + i) = *(uint2*)h;
    *(uint2*)(lo + i) = *(uint2*)l;
}

__global__ __launch_bounds__(256) void convW_kernel(
    const float* __restrict__ W, __nv_bfloat16* __restrict__ Bh,
    __nv_bfloat16* __restrict__ Bl, int K, int N)
{
    __shared__ float t[32][33];
    const int n0 = blockIdx.x * 32, k0 = blockIdx.y * 32;
    const int tx = threadIdx.x, ty = threadIdx.y;
#pragma unroll
    for (int i = 0; i < 32; i += 8)
        t[ty + i][tx] = W[(size_t)(k0 + ty + i) * N + n0 + tx];
    __syncthreads();
#pragma unroll
    for (int i = 0; i < 32; i += 8) {
        float x = t[tx][ty + i];
        __nv_bfloat16 h = __float2bfloat16(x);
        __nv_bfloat16 l = __float2bfloat16(x - __bfloat162float(h));
        size_t o = (size_t)(n0 + ty + i) * K + k0 + tx;
        Bh[o] = h;
        Bl[o] = l;
    }
}

// split qkv (post-RoPE) into bf16 hi/lo; Q columns pre-scaled by 1/sqrt(HD)
__global__ __launch_bounds__(256) void split_qkv_kernel(
    const float* __restrict__ qkv, __nv_bfloat16* __restrict__ hi,
    __nv_bfloat16* __restrict__ lo)
{
    const size_t i = ((size_t)blockIdx.x * 256 + threadIdx.x) * 4;
    float4 v = *(const float4*)(qkv + i);
    const int col = (int)(i % 3072);
    const float sc = (col < 2048) ? 0.08838834764831845f : 1.0f;
    float x[4] = {v.x * sc, v.y * sc, v.z * sc, v.w * sc};
    __nv_bfloat16 h[4], l[4];
#pragma unroll
    for (int j = 0; j < 4; j++) {
        h[j] = __float2bfloat16(x[j]);
        l[j] = __float2bfloat16(x[j] - __bfloat162float(h[j]));
    }
    *(uint2*)(hi + i) = *(uint2*)h;
    *(uint2*)(lo + i) = *(uint2*)l;
}

// ======================= RoPE (unchanged) ==========================
__global__ void rope_kernel(const int* __restrict__ positions, float* __restrict__ qkv) {
    const int token = blockIdx.x;
    const int hh = blockIdx.y;
    const int t = threadIdx.x;
    float* base = qkv + (size_t)token * 3072 +
                  (hh < 16 ? hh * 128 : 2048 + (hh - 16) * 128);
    const float pos = (float)positions[token];
    const float e = (float)(2 * t) * (1.0f / 128.0f);
    const float inv = 1.0f / powf(1000000.0f, e);
    const float ang = pos * inv;
    float sv, cv;
    sincosf(ang, &sv, &cv);
    const float x1 = base[t];
    const float x2 = base[t + 64];
    base[t]      = x1 * cv - x2 * sv;
    base[t + 64] = x2 * cv + x1 * sv;
}

// ======================= HMMA flash attention ==========================
// 64 q-rows x 64 kv chunk, 4 warps (warp = m16 x n64), 3-term bf16 split.
// smem: 6 tiles of 64 x 136 bf16 (stride 272B): Qhi Qlo Khi Klo Vhi Vlo.
#define ASTR 272                    // bytes per 128-col row (136 bf16)
#define ATILE (64 * ASTR)           // 17408
#define SQHI 0
#define SQLO ATILE
#define SKHI (2 * ATILE)
#define SKLO (3 * ATILE)
#define SVHI (4 * ATILE)
#define SVLO (5 * ATILE)
#define ATTN_SMEM (6 * ATILE)       // 104448

__global__ __launch_bounds__(128) void attn_hmma_kernel(
    const __nv_bfloat16* __restrict__ qkvhi, const __nv_bfloat16* __restrict__ qkvlo,
    __nv_bfloat16* __restrict__ Ohi, __nv_bfloat16* __restrict__ Olo)
{
    extern __shared__ char smem[];
    const u32 sb = smem_u32(smem);
    const int tid = threadIdx.x;
    const int wid = tid >> 5, lane = tid & 31;
    const int g = lane >> 2, tig = lane & 3;
    const int mw = wid * 16;
    const int qt = blockIdx.x, h = blockIdx.y, b = blockIdx.z;
    const int q0 = qt * 64, tb = b * 2048, kvh = h >> 2;

    const __nv_bfloat16* qh_g = qkvhi + (size_t)(tb + q0) * 3072 + h * 128;
    const __nv_bfloat16* ql_g = qkvlo + (size_t)(tb + q0) * 3072 + h * 128;
    const __nv_bfloat16* kh_g = qkvhi + (size_t)tb * 3072 + 2048 + kvh * 128;
    const __nv_bfloat16* kl_g = qkvlo + (size_t)tb * 3072 + 2048 + kvh * 128;
    const __nv_bfloat16* vh_g = qkvhi + (size_t)tb * 3072 + 2560 + kvh * 128;
    const __nv_bfloat16* vl_g = qkvlo + (size_t)tb * 3072 + 2560 + kvh * 128;

    // stage Q once (64 x 128 bf16 per tile; 16B chunks)
    for (int i = tid; i < 1024; i += 128) {
        int r = i >> 4, c8 = (i & 15) << 3;
        u32 dst = (u32)(r * ASTR + c8 * 2);
        *(uint4*)(smem + SQHI + dst) = *(const uint4*)(qh_g + (size_t)r * 3072 + c8);
        *(uint4*)(smem + SQLO + dst) = *(const uint4*)(ql_g + (size_t)r * 3072 + c8);
    }

    float o[16][4];
#pragma unroll
    for (int d = 0; d < 16; d++)
#pragma unroll
        for (int r = 0; r < 4; r++) o[d][r] = 0.0f;
    float m_run0 = -3.0e38f, m_run1 = -3.0e38f, l_run0 = 0.0f, l_run1 = 0.0f;

    // ldmatrix base addresses (per-thread components)
    const u32 a_base = sb + SQHI + (u32)((mw + (lane & 15)) * ASTR + ((lane >> 4) << 4));
    const u32 b_base = sb + SKHI + (u32)((lane & 7) * ASTR + (((lane >> 3) & 1) << 4));
    __syncthreads();

    for (int ck = 0; ck <= qt; ck++) {
        const int k0 = ck * 64;
        // stage K/V (cp.async, 16B chunks)
        for (int i = tid; i < 1024; i += 128) {
            int r = i >> 4, c8 = (i & 15) << 3;
            u32 dst = (u32)(r * ASTR + c8 * 2);
            size_t go = (size_t)(k0 + r) * 3072 + c8;
            cp16(sb + SKHI + dst, kh_g + go);
            cp16(sb + SKLO + dst, kl_g + go);
            cp16(sb + SVHI + dst, vh_g + go);
            cp16(sb + SVLO + dst, vl_g + go);
        }
        CP_COMMIT();
        CP_WAIT0();
        __syncthreads();

        // ---- S = Q K^T (3-term) ----
        float s[8][4];
#pragma unroll
        for (int n = 0; n < 8; n++)
#pragma unroll
            for (int r = 0; r < 4; r++) s[n][r] = 0.0f;

#pragma unroll
        for (int kt = 0; kt < 8; kt++) {
            u32 ah[4], al[4];
            LDMX4(ah[0], ah[1], ah[2], ah[3], a_base + kt * 32);
            LDMX4(al[0], al[1], al[2], al[3], a_base + ATILE + kt * 32);
#pragma unroll
            for (int n = 0; n < 8; n++) {
                u32 bh[2], bl[2];
                LDMX2(bh[0], bh[1], b_base + n * (8 * ASTR) + kt * 32);
                LDMX2(bl[0], bl[1], b_base + ATILE + n * (8 * ASTR) + kt * 32);
                MMA16816(s[n], ah, bh);
                MMA16816(s[n], ah, bl);
                MMA16816(s[n], al, bh);
            }
        }

        // ---- causal mask on diagonal chunk ----
        if (ck == qt) {
            const int rA = mw + g, rB = rA + 8;
#pragma unroll
            for (int n = 0; n < 8; n++) {
                int c0 = n * 8 + tig * 2;
                if (c0 > rA) s[n][0] = -3.0e38f;
                if (c0 + 1 > rA) s[n][1] = -3.0e38f;
                if (c0 > rB) s[n][2] = -3.0e38f;
                if (c0 + 1 > rB) s[n][3] = -3.0e38f;
            }
        }

        // ---- online softmax (quad shuffles: lanes of a quad share a row) ----
        float mxA = -3.0e38f, mxB = -3.0e38f;
#pragma unroll
        for (int n = 0; n < 8; n++) {
            mxA = fmaxf(mxA, fmaxf(s[n][0], s[n][1]));
            mxB = fmaxf(mxB, fmaxf(s[n][2], s[n][3]));
        }
        mxA = fmaxf(mxA, __shfl_xor_sync(0xffffffffu, mxA, 1));
        mxA = fmaxf(mxA, __shfl_xor_sync(0xffffffffu, mxA, 2));
        mxB = fmaxf(mxB, __shfl_xor_sync(0xffffffffu, mxB, 1));
        mxB = fmaxf(mxB, __shfl_xor_sync(0xffffffffu, mxB, 2));
        float mnA = fmaxf(m_run0, mxA), mnB = fmaxf(m_run1, mxB);
        float alphaA = __expf(m_run0 - mnA), alphaB = __expf(m_run1 - mnB);
        m_run0 = mnA; m_run1 = mnB;
#pragma unroll
        for (int d = 0; d < 16; d++) {
            o[d][0] *= alphaA; o[d][1] *= alphaA;
            o[d][2] *= alphaB; o[d][3] *= alphaB;
        }
        float lsA = 0.0f, lsB = 0.0f;
#pragma unroll
        for (int n = 0; n < 8; n++) {
            s[n][0] = __expf(s[n][0] - mnA);
            s[n][1] = __expf(s[n][1] - mnA);
            s[n][2] = __expf(s[n][2] - mnB);
            s[n][3] = __expf(s[n][3] - mnB);
            lsA += s[n][0] + s[n][1];
            lsB += s[n][2] + s[n][3];
        }
        lsA += __shfl_xor_sync(0xffffffffu, lsA, 1);
        lsA += __shfl_xor_sync(0xffffffffu, lsA, 2);
        lsB += __shfl_xor_sync(0xffffffffu, lsB, 1);
        lsB += __shfl_xor_sync(0xffffffffu, lsB, 2);
        l_run0 = l_run0 * alphaA + lsA;
        l_run1 = l_run1 * alphaB + lsB;

        // ---- O += P V (3-term); P frags packed from S regs ----
#pragma unroll
        for (int kq = 0; kq < 4; kq++) {
            u32 ph[4], pl[4];
            splitpack(s[2 * kq][0],     s[2 * kq][1],     ph[0], pl[0]);
            splitpack(s[2 * kq][2],     s[2 * kq][3],     ph[1], pl[1]);
            splitpack(s[2 * kq + 1][0], s[2 * kq + 1][1], ph[2], pl[2]);
            splitpack(s[2 * kq + 1][2], s[2 * kq + 1][3], ph[3], pl[3]);
            u32 v_base = sb + SVHI + (u32)((kq * 16 + (lane & 15)) * ASTR);
#pragma unroll
            for (int d = 0; d < 16; d++) {
                u32 bh[2], bl[2];
                LDMX2T(bh[0], bh[1], v_base + d * 16);
                LDMX2T(bl[0], bl[1], v_base + ATILE + d * 16);
                MMA16816(o[d], ph, bh);
                MMA16816(o[d], ph, bl);
                MMA16816(o[d], pl, bh);
            }
        }
        __syncthreads();   // done reading K/V before next chunk overwrites
    }

    // ---- epilogue: divide by l, split to bf16 hi/lo, store ----
    const float invA = 1.0f / l_run0, invB = 1.0f / l_run1;
    const size_t tA = (size_t)(tb + q0 + mw + g);
    const size_t tB = tA + 8;
#pragma unroll
    for (int d = 0; d < 16; d++) {
        const int col = h * 128 + d * 8 + tig * 2;
        u32 h0, l0, h1, l1;
        splitpack(o[d][0] * invA, o[d][1] * invA, h0, l0);
        splitpack(o[d][2] * invB, o[d][3] * invB, h1, l1);
        *(u32*)(Ohi + tA * 2048 + col) = h0;
        *(u32*)(Olo + tA * 2048 + col) = l0;
        *(u32*)(Ohi + tB * 2048 + col) = h1;
        *(u32*)(Olo + tB * 2048 + col) = l1;
    }
}

// ---------------------------------------------------------------------------
extern "C" void kernel_launch(void* const* d_in, const int* in_sizes, int n_in,
                              void* d_out, int out_size)
{
    const int* positions = (const int*)d_in[0];
    const float* hidden  = (const float*)d_in[1];
    const float* Wqkv    = (const float*)d_in[2];
    const float* bqkv    = (const float*)d_in[3];
    const float* Wo      = (const float*)d_in[4];
    float* out = (float*)d_out;

    float* qkv;
    __nv_bfloat16 *qkvhi, *qkvlo, *Ahi, *Alo, *Bhi, *Blo;
    cudaGetSymbolAddress((void**)&qkv, g_qkv);
    cudaGetSymbolAddress((void**)&qkvhi, g_qkvhi);
    cudaGetSymbolAddress((void**)&qkvlo, g_qkvlo);
    cudaGetSymbolAddress((void**)&Ahi, g_Ahi);
    cudaGetSymbolAddress((void**)&Alo, g_Alo);
    cudaGetSymbolAddress((void**)&Bhi, g_Bhi);
    cudaGetSymbolAddress((void**)&Blo, g_Blo);

    cudaFuncSetAttribute(gemm_hmma3_kernel,
                         cudaFuncAttributeMaxDynamicSharedMemorySize, GEMM_SMEM);
    cudaFuncSetAttribute(attn_hmma_kernel,
                         cudaFuncAttributeMaxDynamicSharedMemorySize, ATTN_SMEM);

    // 1) split hidden ; transpose+split Wqkv
    convA_kernel<<<4096 * 2048 / 1024, 256>>>(hidden, Ahi, Alo);
    convW_kernel<<<dim3(3072 / 32, 2048 / 32), dim3(32, 8)>>>(Wqkv, Bhi, Blo, 2048, 3072);

    // 2) QKV GEMM (HMMA) + bias
    gemm_hmma3_kernel<<<dim3(24, 32), 256, GEMM_SMEM>>>(
        Ahi, Alo, Bhi, Blo, bqkv, qkv, 3072, 2048);

    // 3) RoPE (fp32, in place)
    rope_kernel<<<dim3(4096, 20), 64>>>(positions, qkv);

    // 4) split qkv -> bf16 hi/lo (Q pre-scaled)
    split_qkv_kernel<<<4096 * 3072 / 1024, 256>>>(qkv, qkvhi, qkvlo);

    // 5) HMMA flash attention -> writes Ahi/Alo (bf16 hi/lo) directly
    attn_hmma_kernel<<<dim3(32, 16, 2), 128, ATTN_SMEM>>>(qkvhi, qkvlo, Ahi, Alo);

    // 6) transpose+split Wo ; Wo GEMM (HMMA)
    convW_kernel<<<dim3(2048 / 32, 2048 / 32), dim3(32, 8)>>>(Wo, Bhi, Blo, 2048, 2048);
    gemm_hmma3_kernel<<<dim3(16, 32), 256, GEMM_SMEM>>>(
        Ahi, Alo, Bhi, Blo, nullptr, out, 2048, 2048);
}

// round 8
// speedup vs baseline: 3.6617x; 1.0181x over previous
#include <cuda_runtime.h>
#include <cuda_bf16.h>
#include <math.h>

// ---------------------------------------------------------------------------
// Qwen2MoeAttention: B=2, S=2048, H=2048, NH=16, NKV=4, HD=128, theta=1e6
// R8: GEMMs double-buffered with cp.async (K-stage 32, 2-stage pipeline).
//     Attention = R7 HMMA flash (unchanged).
// ---------------------------------------------------------------------------

typedef unsigned long long u64;
typedef unsigned int u32;

static __device__ float g_qkv[4096 * 3072];
static __device__ __nv_bfloat16 g_qkvhi[4096 * 3072];
static __device__ __nv_bfloat16 g_qkvlo[4096 * 3072];
static __device__ __nv_bfloat16 g_Ahi[4096 * 2048];
static __device__ __nv_bfloat16 g_Alo[4096 * 2048];
static __device__ __nv_bfloat16 g_Bhi[3072 * 2048];   // [N][K] K-major
static __device__ __nv_bfloat16 g_Blo[3072 * 2048];

__device__ __forceinline__ u32 smem_u32(const void* p) {
    u32 a;
    asm("{ .reg .u64 t; cvta.to.shared.u64 t, %1; cvt.u32.u64 %0, t; }" : "=r"(a) : "l"(p));
    return a;
}

#define LDMX4(r0, r1, r2, r3, addr) \
    asm volatile("ldmatrix.sync.aligned.m8n8.x4.shared.b16 {%0,%1,%2,%3}, [%4];" \
                 : "=r"(r0), "=r"(r1), "=r"(r2), "=r"(r3) : "r"(addr))
#define LDMX2(r0, r1, addr) \
    asm volatile("ldmatrix.sync.aligned.m8n8.x2.shared.b16 {%0,%1}, [%2];" \
                 : "=r"(r0), "=r"(r1) : "r"(addr))
#define LDMX2T(r0, r1, addr) \
    asm volatile("ldmatrix.sync.aligned.m8n8.x2.trans.shared.b16 {%0,%1}, [%2];" \
                 : "=r"(r0), "=r"(r1) : "r"(addr))
#define MMA16816(d, a, b) \
    asm volatile("mma.sync.aligned.m16n8k16.row.col.f32.bf16.bf16.f32 " \
                 "{%0,%1,%2,%3},{%4,%5,%6,%7},{%8,%9},{%0,%1,%2,%3};" \
                 : "+f"((d)[0]), "+f"((d)[1]), "+f"((d)[2]), "+f"((d)[3]) \
                 : "r"((a)[0]), "r"((a)[1]), "r"((a)[2]), "r"((a)[3]), \
                   "r"((b)[0]), "r"((b)[1]))

__device__ __forceinline__ void cp16(u32 dst, const void* src) {
    asm volatile("cp.async.cg.shared.global [%0], [%1], 16;" :: "r"(dst), "l"(src));
}
#define CP_COMMIT() asm volatile("cp.async.commit_group;")
#define CP_WAIT0()  asm volatile("cp.async.wait_group 0;" ::: "memory")
#define CP_WAIT1()  asm volatile("cp.async.wait_group 1;" ::: "memory")

__device__ __forceinline__ void splitpack(float x, float y, u32& hi, u32& lo) {
    __nv_bfloat162 h = __floats2bfloat162_rn(x, y);
    float hx = __bfloat162float(h.x), hy = __bfloat162float(h.y);
    __nv_bfloat162 l = __floats2bfloat162_rn(x - hx, y - hy);
    hi = *reinterpret_cast<u32*>(&h);
    lo = *reinterpret_cast<u32*>(&l);
}

// ======================= GEMM: double-buffered, K-stage 32 =================
// smem per stage: 4 tiles of 128 rows x 32 bf16, row stride 80 B.
#define SSTR 80
#define STILE (128 * SSTR)          // 10240
#define SSTAGE (4 * STILE)          // 40960
#define SOF_AHI 0
#define SOF_ALO STILE
#define SOF_BHI (2 * STILE)
#define SOF_BLO (3 * STILE)
#define GEMM_SMEM (2 * SSTAGE)      // 81920

__global__ __launch_bounds__(256) void gemm_hmma3_kernel(
    const __nv_bfloat16* __restrict__ Ahi, const __nv_bfloat16* __restrict__ Alo,
    const __nv_bfloat16* __restrict__ Bhi, const __nv_bfloat16* __restrict__ Blo,
    const float* __restrict__ bias, float* __restrict__ C, int N, int K)
{
    extern __shared__ char smem[];
    const u32 sb = smem_u32(smem);
    const int tid = threadIdx.x;
    const int wid = tid >> 5;
    const int lane = tid & 31;
    const int m0 = blockIdx.y * 128, n0 = blockIdx.x * 128;
    const int m0w = (wid >> 2) * 64;
    const int n0w = (wid & 3) * 32;

    const int a_row = lane & 15;
    const int a_kh2 = (lane >> 4) << 4;            // 0 or 16 bytes
    const int b_row = lane & 7;
    const int b_kh2 = ((lane >> 3) & 1) << 4;      // 0 or 16 bytes

    // per-thread load indices: 512 16B-chunks per tile, 2 per thread
    const int l_row0 = tid >> 2, l_c0 = (tid & 3) << 4;          // chunk 0
    const int l_row1 = (tid + 256) >> 2, l_c1 = ((tid + 256) & 3) << 4;

    float acc[4][4][4];
#pragma unroll
    for (int tm = 0; tm < 4; tm++)
#pragma unroll
        for (int tn = 0; tn < 4; tn++)
#pragma unroll
            for (int r = 0; r < 4; r++) acc[tm][tn][r] = 0.0f;

    const int nstages = K >> 5;

    // ---- stage loader (cp.async) ----
    auto load_stage = [&](int buf, int ks) {
        const u32 base = sb + buf * SSTAGE;
        u32 so0 = (u32)(l_row0 * SSTR + l_c0);
        u32 so1 = (u32)(l_row1 * SSTR + l_c1);
        size_t ga0 = (size_t)(m0 + l_row0) * K + ks + (l_c0 >> 1);
        size_t ga1 = (size_t)(m0 + l_row1) * K + ks + (l_c1 >> 1);
        size_t gb0 = (size_t)(n0 + l_row0) * K + ks + (l_c0 >> 1);
        size_t gb1 = (size_t)(n0 + l_row1) * K + ks + (l_c1 >> 1);
        cp16(base + SOF_AHI + so0, Ahi + ga0);
        cp16(base + SOF_AHI + so1, Ahi + ga1);
        cp16(base + SOF_ALO + so0, Alo + ga0);
        cp16(base + SOF_ALO + so1, Alo + ga1);
        cp16(base + SOF_BHI + so0, Bhi + gb0);
        cp16(base + SOF_BHI + so1, Bhi + gb1);
        cp16(base + SOF_BLO + so0, Blo + gb0);
        cp16(base + SOF_BLO + so1, Blo + gb1);
    };

    load_stage(0, 0);
    CP_COMMIT();

    for (int s = 0; s < nstages; s++) {
        const int buf = s & 1;
        if (s + 1 < nstages) {
            load_stage(buf ^ 1, (s + 1) << 5);
            CP_COMMIT();
            CP_WAIT1();
        } else {
            CP_WAIT0();
        }
        __syncthreads();

        const u32 base = sb + buf * SSTAGE;
#pragma unroll
        for (int k16 = 0; k16 < 2; k16++) {
            const int kb = k16 << 5;   // 32 bytes per k16
            u32 ahi[4][4], alo[4][4], bhi[4][2], blo[4][2];
#pragma unroll
            for (int tm = 0; tm < 4; tm++) {
                u32 ao = (u32)((m0w + tm * 16 + a_row) * SSTR + kb + a_kh2);
                LDMX4(ahi[tm][0], ahi[tm][1], ahi[tm][2], ahi[tm][3], base + SOF_AHI + ao);
                LDMX4(alo[tm][0], alo[tm][1], alo[tm][2], alo[tm][3], base + SOF_ALO + ao);
            }
#pragma unroll
            for (int tn = 0; tn < 4; tn++) {
                u32 bo = (u32)((n0w + tn * 8 + b_row) * SSTR + kb + b_kh2);
                LDMX2(bhi[tn][0], bhi[tn][1], base + SOF_BHI + bo);
                LDMX2(blo[tn][0], blo[tn][1], base + SOF_BLO + bo);
            }
#pragma unroll
            for (int tm = 0; tm < 4; tm++)
#pragma unroll
                for (int tn = 0; tn < 4; tn++) {
                    MMA16816(acc[tm][tn], ahi[tm], bhi[tn]);
                    MMA16816(acc[tm][tn], ahi[tm], blo[tn]);
                    MMA16816(acc[tm][tn], alo[tm], bhi[tn]);
                }
        }
        __syncthreads();
    }

#pragma unroll
    for (int tm = 0; tm < 4; tm++) {
        const int r0 = m0 + m0w + tm * 16 + (lane >> 2);
#pragma unroll
        for (int tn = 0; tn < 4; tn++) {
            const int c = n0 + n0w + tn * 8 + (lane & 3) * 2;
            float b0 = 0.0f, b1 = 0.0f;
            if (bias) { b0 = bias[c]; b1 = bias[c + 1]; }
            *(float2*)(C + (size_t)r0 * N + c) =
                make_float2(acc[tm][tn][0] + b0, acc[tm][tn][1] + b1);
            *(float2*)(C + (size_t)(r0 + 8) * N + c) =
                make_float2(acc[tm][tn][2] + b0, acc[tm][tn][3] + b1);
        }
    }
}

// ======================= conversions ==========================
__global__ __launch_bounds__(256) void convA_kernel(
    const float* __restrict__ A, __nv_bfloat16* __restrict__ hi,
    __nv_bfloat16* __restrict__ lo)
{
    const int i = (blockIdx.x * 256 + threadIdx.x) * 4;
    float4 v = *(const float4*)(A + i);
    __nv_bfloat16 h[4], l[4];
    float x[4] = {v.x, v.y, v.z, v.w};
#pragma unroll
    for (int j = 0; j < 4; j++) {
        h[j] = __float2bfloat16(x[j]);
        l[j] = __float2bfloat16(x[j] - __bfloat162float(h[j]));
    }
    *(uint2*)(hi + i) = *(uint2*)h;
    *(uint2*)(lo + i) = *(uint2*)l;
}

__global__ __launch_bounds__(256) void convW_kernel(
    const float* __restrict__ W, __nv_bfloat16* __restrict__ Bh,
    __nv_bfloat16* __restrict__ Bl, int K, int N)
{
    __shared__ float t[32][33];
    const int n0 = blockIdx.x * 32, k0 = blockIdx.y * 32;
    const int tx = threadIdx.x, ty = threadIdx.y;
#pragma unroll
    for (int i = 0; i < 32; i += 8)
        t[ty + i][tx] = W[(size_t)(k0 + ty + i) * N + n0 + tx];
    __syncthreads();
#pragma unroll
    for (int i = 0; i < 32; i += 8) {
        float x = t[tx][ty + i];
        __nv_bfloat16 h = __float2bfloat16(x);
        __nv_bfloat16 l = __float2bfloat16(x - __bfloat162float(h));
        size_t o = (size_t)(n0 + ty + i) * K + k0 + tx;
        Bh[o] = h;
        Bl[o] = l;
    }
}

__global__ __launch_bounds__(256) void split_qkv_kernel(
    const float* __restrict__ qkv, __nv_bfloat16* __restrict__ hi,
    __nv_bfloat16* __restrict__ lo)
{
    const size_t i = ((size_t)blockIdx.x * 256 + threadIdx.x) * 4;
    float4 v = *(const float4*)(qkv + i);
    const int col = (int)(i % 3072);
    const float sc = (col < 2048) ? 0.08838834764831845f : 1.0f;
    float x[4] = {v.x * sc, v.y * sc, v.z * sc, v.w * sc};
    __nv_bfloat16 h[4], l[4];
#pragma unroll
    for (int j = 0; j < 4; j++) {
        h[j] = __float2bfloat16(x[j]);
        l[j] = __float2bfloat16(x[j] - __bfloat162float(h[j]));
    }
    *(uint2*)(hi + i) = *(uint2*)h;
    *(uint2*)(lo + i) = *(uint2*)l;
}

// ======================= RoPE ==========================
__global__ void rope_kernel(const int* __restrict__ positions, float* __restrict__ qkv) {
    const int token = blockIdx.x;
    const int hh = blockIdx.y;
    const int t = threadIdx.x;
    float* base = qkv + (size_t)token * 3072 +
                  (hh < 16 ? hh * 128 : 2048 + (hh - 16) * 128);
    const float pos = (float)positions[token];
    const float e = (float)(2 * t) * (1.0f / 128.0f);
    const float inv = 1.0f / powf(1000000.0f, e);
    const float ang = pos * inv;
    float sv, cv;
    sincosf(ang, &sv, &cv);
    const float x1 = base[t];
    const float x2 = base[t + 64];
    base[t]      = x1 * cv - x2 * sv;
    base[t + 64] = x2 * cv + x1 * sv;
}

// ======================= HMMA flash attention (R7, unchanged) ==============
#define ASTR 272
#define ATILE (64 * ASTR)
#define SQHI 0
#define SQLO ATILE
#define SKHI (2 * ATILE)
#define SKLO (3 * ATILE)
#define SVHI (4 * ATILE)
#define SVLO (5 * ATILE)
#define ATTN_SMEM (6 * ATILE)

__global__ __launch_bounds__(128) void attn_hmma_kernel(
    const __nv_bfloat16* __restrict__ qkvhi, const __nv_bfloat16* __restrict__ qkvlo,
    __nv_bfloat16* __restrict__ Ohi, __nv_bfloat16* __restrict__ Olo)
{
    extern __shared__ char smem[];
    const u32 sb = smem_u32(smem);
    const int tid = threadIdx.x;
    const int wid = tid >> 5, lane = tid & 31;
    const int g = lane >> 2, tig = lane & 3;
    const int mw = wid * 16;
    const int qt = blockIdx.x, h = blockIdx.y, b = blockIdx.z;
    const int q0 = qt * 64, tb = b * 2048, kvh = h >> 2;

    const __nv_bfloat16* qh_g = qkvhi + (size_t)(tb + q0) * 3072 + h * 128;
    const __nv_bfloat16* ql_g = qkvlo + (size_t)(tb + q0) * 3072 + h * 128;
    const __nv_bfloat16* kh_g = qkvhi + (size_t)tb * 3072 + 2048 + kvh * 128;
    const __nv_bfloat16* kl_g = qkvlo + (size_t)tb * 3072 + 2048 + kvh * 128;
    const __nv_bfloat16* vh_g = qkvhi + (size_t)tb * 3072 + 2560 + kvh * 128;
    const __nv_bfloat16* vl_g = qkvlo + (size_t)tb * 3072 + 2560 + kvh * 128;

    for (int i = tid; i < 1024; i += 128) {
        int r = i >> 4, c8 = (i & 15) << 3;
        u32 dst = (u32)(r * ASTR + c8 * 2);
        *(uint4*)(smem + SQHI + dst) = *(const uint4*)(qh_g + (size_t)r * 3072 + c8);
        *(uint4*)(smem + SQLO + dst) = *(const uint4*)(ql_g + (size_t)r * 3072 + c8);
    }

    float o[16][4];
#pragma unroll
    for (int d = 0; d < 16; d++)
#pragma unroll
        for (int r = 0; r < 4; r++) o[d][r] = 0.0f;
    float m_run0 = -3.0e38f, m_run1 = -3.0e38f, l_run0 = 0.0f, l_run1 = 0.0f;

    const u32 a_base = sb + SQHI + (u32)((mw + (lane & 15)) * ASTR + ((lane >> 4) << 4));
    const u32 b_base = sb + SKHI + (u32)((lane & 7) * ASTR + (((lane >> 3) & 1) << 4));
    __syncthreads();

    for (int ck = 0; ck <= qt; ck++) {
        const int k0 = ck * 64;
        for (int i = tid; i < 1024; i += 128) {
            int r = i >> 4, c8 = (i & 15) << 3;
            u32 dst = (u32)(r * ASTR + c8 * 2);
            size_t go = (size_t)(k0 + r) * 3072 + c8;
            cp16(sb + SKHI + dst, kh_g + go);
            cp16(sb + SKLO + dst, kl_g + go);
            cp16(sb + SVHI + dst, vh_g + go);
            cp16(sb + SVLO + dst, vl_g + go);
        }
        CP_COMMIT();
        CP_WAIT0();
        __syncthreads();

        float s[8][4];
#pragma unroll
        for (int n = 0; n < 8; n++)
#pragma unroll
            for (int r = 0; r < 4; r++) s[n][r] = 0.0f;

#pragma unroll
        for (int kt = 0; kt < 8; kt++) {
            u32 ah[4], al[4];
            LDMX4(ah[0], ah[1], ah[2], ah[3], a_base + kt * 32);
            LDMX4(al[0], al[1], al[2], al[3], a_base + ATILE + kt * 32);
#pragma unroll
            for (int n = 0; n < 8; n++) {
                u32 bh[2], bl[2];
                LDMX2(bh[0], bh[1], b_base + n * (8 * ASTR) + kt * 32);
                LDMX2(bl[0], bl[1], b_base + ATILE + n * (8 * ASTR) + kt * 32);
                MMA16816(s[n], ah, bh);
                MMA16816(s[n], ah, bl);
                MMA16816(s[n], al, bh);
            }
        }

        if (ck == qt) {
            const int rA = mw + g, rB = rA + 8;
#pragma unroll
            for (int n = 0; n < 8; n++) {
                int c0 = n * 8 + tig * 2;
                if (c0 > rA) s[n][0] = -3.0e38f;
                if (c0 + 1 > rA) s[n][1] = -3.0e38f;
                if (c0 > rB) s[n][2] = -3.0e38f;
                if (c0 + 1 > rB) s[n][3] = -3.0e38f;
            }
        }

        float mxA = -3.0e38f, mxB = -3.0e38f;
#pragma unroll
        for (int n = 0; n < 8; n++) {
            mxA = fmaxf(mxA, fmaxf(s[n][0], s[n][1]));
            mxB = fmaxf(mxB, fmaxf(s[n][2], s[n][3]));
        }
        mxA = fmaxf(mxA, __shfl_xor_sync(0xffffffffu, mxA, 1));
        mxA = fmaxf(mxA, __shfl_xor_sync(0xffffffffu, mxA, 2));
        mxB = fmaxf(mxB, __shfl_xor_sync(0xffffffffu, mxB, 1));
        mxB = fmaxf(mxB, __shfl_xor_sync(0xffffffffu, mxB, 2));
        float mnA = fmaxf(m_run0, mxA), mnB = fmaxf(m_run1, mxB);
        float alphaA = __expf(m_run0 - mnA), alphaB = __expf(m_run1 - mnB);
        m_run0 = mnA; m_run1 = mnB;
#pragma unroll
        for (int d = 0; d < 16; d++) {
            o[d][0] *= alphaA; o[d][1] *= alphaA;
            o[d][2] *= alphaB; o[d][3] *= alphaB;
        }
        float lsA = 0.0f, lsB = 0.0f;
#pragma unroll
        for (int n = 0; n < 8; n++) {
            s[n][0] = __expf(s[n][0] - mnA);
            s[n][1] = __expf(s[n][1] - mnA);
            s[n][2] = __expf(s[n][2] - mnB);
            s[n][3] = __expf(s[n][3] - mnB);
            lsA += s[n][0] + s[n][1];
            lsB += s[n][2] + s[n][3];
        }
        lsA += __shfl_xor_sync(0xffffffffu, lsA, 1);
        lsA += __shfl_xor_sync(0xffffffffu, lsA, 2);
        lsB += __shfl_xor_sync(0xffffffffu, lsB, 1);
        lsB += __shfl_xor_sync(0xffffffffu, lsB, 2);
        l_run0 = l_run0 * alphaA + lsA;
        l_run1 = l_run1 * alphaB + lsB;

#pragma unroll
        for (int kq = 0; kq < 4; kq++) {
            u32 ph[4], pl[4];
            splitpack(s[2 * kq][0],     s[2 * kq][1],     ph[0], pl[0]);
            splitpack(s[2 * kq][2],     s[2 * kq][3],     ph[1], pl[1]);
            splitpack(s[2 * kq + 1][0], s[2 * kq + 1][1], ph[2], pl[2]);
            splitpack(s[2 * kq + 1][2], s[2 * kq + 1][3], ph[3], pl[3]);
            u32 v_base = sb + SVHI + (u32)((kq * 16 + (lane & 15)) * ASTR);
#pragma unroll
            for (int d = 0; d < 16; d++) {
                u32 bh[2], bl[2];
                LDMX2T(bh[0], bh[1], v_base + d * 16);
                LDMX2T(bl[0], bl[1], v_base + ATILE + d * 16);
                MMA16816(o[d], ph, bh);
                MMA16816(o[d], ph, bl);
                MMA16816(o[d], pl, bh);
            }
        }
        __syncthreads();
    }

    const float invA = 1.0f / l_run0, invB = 1.0f / l_run1;
    const size_t tA = (size_t)(tb + q0 + mw + g);
    const size_t tB = tA + 8;
#pragma unroll
    for (int d = 0; d < 16; d++) {
        const int col = h * 128 + d * 8 + tig * 2;
        u32 h0, l0, h1, l1;
        splitpack(o[d][0] * invA, o[d][1] * invA, h0, l0);
        splitpack(o[d][2] * invB, o[d][3] * invB, h1, l1);
        *(u32*)(Ohi + tA * 2048 + col) = h0;
        *(u32*)(Olo + tA * 2048 + col) = l0;
        *(u32*)(Ohi + tB * 2048 + col) = h1;
        *(u32*)(Olo + tB * 2048 + col) = l1;
    }
}

// ---------------------------------------------------------------------------
extern "C" void kernel_launch(void* const* d_in, const int* in_sizes, int n_in,
                              void* d_out, int out_size)
{
    const int* positions = (const int*)d_in[0];
    const float* hidden  = (const float*)d_in[1];
    const float* Wqkv    = (const float*)d_in[2];
    const float* bqkv    = (const float*)d_in[3];
    const float* Wo      = (const float*)d_in[4];
    float* out = (float*)d_out;

    float* qkv;
    __nv_bfloat16 *qkvhi, *qkvlo, *Ahi, *Alo, *Bhi, *Blo;
    cudaGetSymbolAddress((void**)&qkv, g_qkv);
    cudaGetSymbolAddress((void**)&qkvhi, g_qkvhi);
    cudaGetSymbolAddress((void**)&qkvlo, g_qkvlo);
    cudaGetSymbolAddress((void**)&Ahi, g_Ahi);
    cudaGetSymbolAddress((void**)&Alo, g_Alo);
    cudaGetSymbolAddress((void**)&Bhi, g_Bhi);
    cudaGetSymbolAddress((void**)&Blo, g_Blo);

    cudaFuncSetAttribute(gemm_hmma3_kernel,
                         cudaFuncAttributeMaxDynamicSharedMemorySize, GEMM_SMEM);
    cudaFuncSetAttribute(attn_hmma_kernel,
                         cudaFuncAttributeMaxDynamicSharedMemorySize, ATTN_SMEM);

    convA_kernel<<<4096 * 2048 / 1024, 256>>>(hidden, Ahi, Alo);
    convW_kernel<<<dim3(3072 / 32, 2048 / 32), dim3(32, 8)>>>(Wqkv, Bhi, Blo, 2048, 3072);

    gemm_hmma3_kernel<<<dim3(24, 32), 256, GEMM_SMEM>>>(
        Ahi, Alo, Bhi, Blo, bqkv, qkv, 3072, 2048);

    rope_kernel<<<dim3(4096, 20), 64>>>(positions, qkv);

    split_qkv_kernel<<<4096 * 3072 / 1024, 256>>>(qkv, qkvhi, qkvlo);

    attn_hmma_kernel<<<dim3(32, 16, 2), 128, ATTN_SMEM>>>(qkvhi, qkvlo, Ahi, Alo);

    convW_kernel<<<dim3(2048 / 32, 2048 / 32), dim3(32, 8)>>>(Wo, Bhi, Blo, 2048, 2048);
    gemm_hmma3_kernel<<<dim3(16, 32), 256, GEMM_SMEM>>>(
        Ahi, Alo, Bhi, Blo, nullptr, out, 2048, 2048);
}